// round 15
// baseline (speedup 1.0000x reference)
#include <cuda_runtime.h>
#include <cuda_fp16.h>
#include <math.h>

// Levels: RES = {128, 256, 512, 1024}, C=4 channels, 3 planes per level.
//
// Fused sampling table (fp16, lc-prefolded, zero-bordered):
//  - Levels 0-2: quad layout (16.6MB total). Quad[y][s] = 2 uint4 (32B).
//  - Level 3:    pair layout (50MB). P[ye][s] = 1 uint4 (16B).
// enc is SPLIT BY LEVEL GROUP so each kernel's gather working set stays
// L2-resident under its own output write stream:
//   encB: level 3 only   (50MB table + 50MB output slice)
//   encA: levels 0-2     (16.6MB tables + 144MB contiguous output slice)
#define NLEV 4

// quads: 2*(49923+198147+789507) = 2075154 uint4 ; pairs3: 3*1026*1025 = 3154950
__device__ __align__(32) uint4 g_table[5230104];   // ~84MB
__device__ __align__(16) float g_linec[48];        // [l][p][c]

__constant__ int c_res[NLEV]  = {128, 256, 512, 1024};
__constant__ int c_qlvl[3]    = {0, 49923, 248070};          // quad-index offsets (lvl 0-2)

// encA per-sample (s = l*3+p, l<3) addressing constants (uint4-element units)
__constant__ int c_aebase[9] = {
    0,      33282,   66564,             // lvl0: 2*qbase
    99846,  231944,  364042,            // lvl1
    496140, 1022478, 1548816};          // lvl2
__constant__ int   c_aey[9] = {258,258,258, 514,514,514, 1026,1026,1026};
__constant__ float c_ahR[9] = {64.f,64.f,64.f, 128.f,128.f,128.f, 256.f,256.f,256.f};
// encB (level 3): base = 2075154 + p*1051650, rp = 1025, hR = 512
__constant__ int c_b3[3] = {2075154, 3126804, 4178454};

// bit-reinterpret helpers (no-op in SASS)
__device__ __forceinline__ unsigned int h2_as_u32(__half2 h) {
    return *reinterpret_cast<unsigned int*>(&h);
}
__device__ __forceinline__ __half2 u32_as_h2(unsigned int u) {
    return *reinterpret_cast<__half2*>(&u);
}

// ---------------------------------------------------------------------------
// Line constants: triline grid_sample degenerates to
//   linec[l,p,c] = 0.5*(tl[p,c,R/2-1,0] + tl[p,c,R/2,0])
// ---------------------------------------------------------------------------
__global__ void linec_kernel(const float* __restrict__ t0, const float* __restrict__ t1,
                             const float* __restrict__ t2, const float* __restrict__ t3) {
    int i = threadIdx.x;
    if (i >= 48) return;
    int l  = i / 12;
    int pc = i % 12;            // p*4 + c
    const float* t = (l == 0) ? t0 : (l == 1) ? t1 : (l == 2) ? t2 : t3;
    int r = c_res[l];
    g_linec[i] = 0.5f * (t[pc * r + r / 2 - 1] + t[pc * r + r / 2]);
}

// ---------------------------------------------------------------------------
// Vectorized quad builder (levels 0-2): each thread builds 4 consecutive quads.
// grid: (ceil((512/4+1)/128), 513, 9) ; lvl = z/3, p = z%3
// ---------------------------------------------------------------------------
__global__ __launch_bounds__(128)
void quadv_kernel(const float* __restrict__ inA, const float* __restrict__ inB,
                  const float* __restrict__ inC) {
    int zi  = blockIdx.z;
    int lvl = zi / 3;
    int p   = zi % 3;
    int R   = c_res[lvl];
    int y   = blockIdx.y;
    if (y > R) return;
    int s0 = (blockIdx.x * blockDim.x + threadIdx.x) * 4;
    if (s0 > R) return;
    const float* in = (lvl == 0) ? inA : (lvl == 1) ? inB : inC;

    int rr = R * R;
    const float* bp = in + (size_t)(p * 4) * rr;
    const float* lc = g_linec + lvl * 12 + p * 4;

    int ylo = y - 1, yhi = y;
    bool ylov  = (ylo >= 0);
    bool yhiv  = (yhi < R);
    bool fullv = (s0 + 4 <= R);
    bool m1v   = (s0 >= 1);

    float wlo[4][5], whi[4][5];
#pragma unroll
    for (int c = 0; c < 4; c++) {
        float l_ = lc[c];
        const float* rl = bp + (size_t)c * rr + (size_t)ylo * R;
        const float* rh = bp + (size_t)c * rr + (size_t)yhi * R;
        float  m1l = (ylov && m1v) ? __ldg(rl + s0 - 1) : 0.f;
        float  m1h = (yhiv && m1v) ? __ldg(rh + s0 - 1) : 0.f;
        float4 vl = make_float4(0.f, 0.f, 0.f, 0.f);
        float4 vh = make_float4(0.f, 0.f, 0.f, 0.f);
        if (ylov && fullv) vl = __ldg(reinterpret_cast<const float4*>(rl + s0));
        if (yhiv && fullv) vh = __ldg(reinterpret_cast<const float4*>(rh + s0));
        wlo[c][0] = m1l * l_; wlo[c][1] = vl.x * l_; wlo[c][2] = vl.y * l_;
        wlo[c][3] = vl.z * l_; wlo[c][4] = vl.w * l_;
        whi[c][0] = m1h * l_; whi[c][1] = vh.x * l_; whi[c][2] = vh.y * l_;
        whi[c][3] = vh.z * l_; whi[c][4] = vh.w * l_;
    }

    int rp = R + 1;
    int qbase = c_qlvl[lvl] + p * rp * rp + y * rp + s0;
#pragma unroll
    for (int j = 0; j < 4; j++) {
        if (s0 + j > R) break;
        uint4 t0, t1;
        t0.x = h2_as_u32(__halves2half2(__float2half_rn(wlo[0][j]),     __float2half_rn(wlo[1][j])));
        t0.y = h2_as_u32(__halves2half2(__float2half_rn(wlo[2][j]),     __float2half_rn(wlo[3][j])));
        t0.z = h2_as_u32(__halves2half2(__float2half_rn(wlo[0][j + 1]), __float2half_rn(wlo[1][j + 1])));
        t0.w = h2_as_u32(__halves2half2(__float2half_rn(wlo[2][j + 1]), __float2half_rn(wlo[3][j + 1])));
        t1.x = h2_as_u32(__halves2half2(__float2half_rn(whi[0][j]),     __float2half_rn(whi[1][j])));
        t1.y = h2_as_u32(__halves2half2(__float2half_rn(whi[2][j]),     __float2half_rn(whi[3][j])));
        t1.z = h2_as_u32(__halves2half2(__float2half_rn(whi[0][j + 1]), __float2half_rn(whi[1][j + 1])));
        t1.w = h2_as_u32(__halves2half2(__float2half_rn(whi[2][j + 1]), __float2half_rn(whi[3][j + 1])));
        g_table[2 * (qbase + j)]     = t0;
        g_table[2 * (qbase + j) + 1] = t1;
    }
}

// ---------------------------------------------------------------------------
// Vectorized pair builder (level 3, R=1024): each thread builds 4 pairs.
// grid: (ceil(257/128), 1026, 3)
// ---------------------------------------------------------------------------
__global__ __launch_bounds__(128)
void pairv_kernel(const float* __restrict__ in) {
    const int R = 1024, rp = 1025;
    int ye = blockIdx.y;                                 // 0..R+1
    int p  = blockIdx.z;
    int s0 = (blockIdx.x * blockDim.x + threadIdx.x) * 4;
    if (s0 > R) return;
    int y  = ye - 1;
    int rr = R * R;
    bool yok   = (y >= 0) && (y < R);
    bool fullv = yok && (s0 + 4 <= R);
    bool m1v   = yok && (s0 >= 1);
    const float* bp = in + (size_t)(p * 4) * rr + (size_t)y * R;
    const float* lc = g_linec + 3 * 12 + p * 4;

    float w[4][5];
#pragma unroll
    for (int c = 0; c < 4; c++) {
        float l_ = lc[c];
        const float* cp = bp + (size_t)c * rr;
        float  m1 = m1v ? __ldg(cp + s0 - 1) : 0.f;
        float4 v  = make_float4(0.f, 0.f, 0.f, 0.f);
        if (fullv) v = __ldg(reinterpret_cast<const float4*>(cp + s0));
        w[c][0] = m1 * l_; w[c][1] = v.x * l_; w[c][2] = v.y * l_;
        w[c][3] = v.z * l_; w[c][4] = v.w * l_;
    }

    int base = 2075154 + p * 1051650 + ye * rp + s0;
#pragma unroll
    for (int j = 0; j < 4; j++) {
        if (s0 + j > R) break;
        uint4 t;
        t.x = h2_as_u32(__halves2half2(__float2half_rn(w[0][j]),     __float2half_rn(w[1][j])));
        t.y = h2_as_u32(__halves2half2(__float2half_rn(w[2][j]),     __float2half_rn(w[3][j])));
        t.z = h2_as_u32(__halves2half2(__float2half_rn(w[0][j + 1]), __float2half_rn(w[1][j + 1])));
        t.w = h2_as_u32(__halves2half2(__float2half_rn(w[2][j + 1]), __float2half_rn(w[3][j + 1])));
        g_table[base + j] = t;
    }
}

// ---------------------------------------------------------------------------
// Shared per-sample body: lane pair (even=row0, odd=row1) computes one
// bilinear sample; even lane yields channels 0-1, odd lane channels 2-3.
// ---------------------------------------------------------------------------
__device__ __forceinline__ float2 sample_pairlane(int elem, float wx, float wy, int row) {
    uint4 tq = __ldg(&g_table[elem]);
    __half2 wx2 = __float2half2_rn(wx);
    __half2 a01 = u32_as_h2(tq.x), a23 = u32_as_h2(tq.y);   // x0
    __half2 b01 = u32_as_h2(tq.z), b23 = u32_as_h2(tq.w);   // x1
    __half2 r01 = __hfma2(__hsub2(b01, a01), wx2, a01);
    __half2 r23 = __hfma2(__hsub2(b23, a23), wx2, a23);
    unsigned o01 = __shfl_xor_sync(0xffffffffu, h2_as_u32(r01), 1);
    unsigned o23 = __shfl_xor_sync(0xffffffffu, h2_as_u32(r23), 1);
    __half2 lo = (row == 0) ? r01 : u32_as_h2(o23);
    __half2 hi = (row == 0) ? u32_as_h2(o01) : r23;
    __half2 wy2 = __float2half2_rn(wy);
    __half2 vv2 = __hfma2(__hsub2(hi, lo), wy2, lo);
    return __half22float2(vv2);
}

// ---------------------------------------------------------------------------
// encA: levels 0-2. 2 threads per sample, 9 samples per point (18 thr/point).
// Output bytes [0,144) of each point's 192B record (contiguous slice).
// ---------------------------------------------------------------------------
__global__ __launch_bounds__(256)
void encA_kernel(const float* __restrict__ x, float* __restrict__ out, int N) {
    int tid  = blockIdx.x * blockDim.x + threadIdx.x;
    int k    = tid >> 1;
    int row  = tid & 1;
    int point = k / 9;
    int s     = k - point * 9;        // sample id 0..8  (l = s/3, p = s%3)
    bool live = (point < N);
    if (point >= N) point = N - 1;

    const float* xp = x + 3 * (size_t)point;
    float px = fmaf(2.f, __ldg(xp + 0), -1.f);
    float py = fmaf(2.f, __ldg(xp + 1), -1.f);
    float pz = fmaf(2.f, __ldg(xp + 2), -1.f);

    int p = s - (s / 3) * 3;
    float u  = (p == 0) ? px : (p == 1) ? py : pz;
    float v  = (p == 0) ? pz : (p == 1) ? px : py;
    float wl = fmaf(-0.5f, fabsf(u), 1.f);

    float hR = c_ahR[s];
    float fx = fmaf(u, hR, hR - 0.5f);
    float fy = fmaf(v, hR, hR - 0.5f);
    float fx0 = floorf(fx), fy0 = floorf(fy);
    float wx = fx - fx0,   wy = fy - fy0;
    int ix = (int)fx0, iy = (int)fy0;

    int elem = c_aebase[s] + (iy + 1) * c_aey[s] + (ix + 1) * 2 + row;
    float2 f = sample_pairlane(elem, wx, wy, row);

    float2 res = make_float2(f.x * wl, f.y * wl);
    float2* o2 = reinterpret_cast<float2*>(out + (size_t)point * 48);
    if (live) __stcs(&o2[s * 2 + row], res);
}

// ---------------------------------------------------------------------------
// encB: level 3 (pair table). 2 threads per sample, 3 samples per point.
// Output bytes [144,192) of each point's record.
// ---------------------------------------------------------------------------
__global__ __launch_bounds__(256)
void encB_kernel(const float* __restrict__ x, float* __restrict__ out, int N) {
    int tid  = blockIdx.x * blockDim.x + threadIdx.x;
    int k    = tid >> 1;
    int row  = tid & 1;
    int point = k / 3;
    int p     = k - point * 3;
    bool live = (point < N);
    if (point >= N) point = N - 1;

    const float* xp = x + 3 * (size_t)point;
    float px = fmaf(2.f, __ldg(xp + 0), -1.f);
    float py = fmaf(2.f, __ldg(xp + 1), -1.f);
    float pz = fmaf(2.f, __ldg(xp + 2), -1.f);

    float u  = (p == 0) ? px : (p == 1) ? py : pz;
    float v  = (p == 0) ? pz : (p == 1) ? px : py;
    float wl = fmaf(-0.5f, fabsf(u), 1.f);

    const float hR = 512.f;
    const int   rp = 1025;
    float fx = fmaf(u, hR, hR - 0.5f);
    float fy = fmaf(v, hR, hR - 0.5f);
    float fx0 = floorf(fx), fy0 = floorf(fy);
    float wx = fx - fx0,   wy = fy - fy0;
    int ix = (int)fx0, iy = (int)fy0;

    // pair layout: row y0 at (iy+1), row y1 at (iy+2)
    int elem = c_b3[p] + (iy + 1 + row) * rp + (ix + 1);
    float2 f = sample_pairlane(elem, wx, wy, row);

    float2 res = make_float2(f.x * wl, f.y * wl);
    float2* o2 = reinterpret_cast<float2*>(out + (size_t)point * 48);
    if (live) __stcs(&o2[(9 + p) * 2 + row], res);
}

// ---------------------------------------------------------------------------
// Launch: identify inputs by size (robust to metadata ordering)
// ---------------------------------------------------------------------------
extern "C" void kernel_launch(void* const* d_in, const int* in_sizes, int n_in,
                              void* d_out, int out_size) {
    // triplane_l : 12*R*R = 196608, 786432, 3145728, 12582912
    // triline_l  : 12*R   = 1536, 3072, 6144, 12288
    // x          : 3*N    = 3145728 (ambiguous with triplane_2)
    int tp_idx[NLEV] = {-1, -1, -1, -1};
    int tl_idx[NLEV] = {-1, -1, -1, -1};
    int amb[2]; int n_amb = 0;
    int x_idx = -1;

    for (int i = 0; i < n_in; i++) {
        int s = in_sizes[i];
        if      (s == 196608)   tp_idx[0] = i;
        else if (s == 786432)   tp_idx[1] = i;
        else if (s == 12582912) tp_idx[3] = i;
        else if (s == 1536)     tl_idx[0] = i;
        else if (s == 3072)     tl_idx[1] = i;
        else if (s == 6144)     tl_idx[2] = i;
        else if (s == 12288)    tl_idx[3] = i;
        else if (s == 3145728)  { if (n_amb < 2) amb[n_amb++] = i; }
        else if (x_idx < 0)     x_idx = i;
    }
    if (n_amb == 1) {
        tp_idx[2] = amb[0];
    } else if (n_amb == 2) {
        // triplane_0..3 occupy contiguous ascending indices in either ordering
        int a = amb[0], b = amb[1];
        if (a > tp_idx[1] && a < tp_idx[3]) { tp_idx[2] = a; x_idx = b; }
        else                                { tp_idx[2] = b; x_idx = a; }
    }
    if (x_idx < 0) x_idx = 0;

    const float* x = (const float*)d_in[x_idx];
    int N = in_sizes[x_idx] / 3;

    // 1: line constants (folded into tables)
    linec_kernel<<<1, 64>>>((const float*)d_in[tl_idx[0]], (const float*)d_in[tl_idx[1]],
                            (const float*)d_in[tl_idx[2]], (const float*)d_in[tl_idx[3]]);

    // 2: quad tables, levels 0-2
    {
        dim3 grid((512 / 4 + 1 + 127) / 128, 513, 9);   // (2, 513, 9)
        quadv_kernel<<<grid, 128>>>((const float*)d_in[tp_idx[0]],
                                    (const float*)d_in[tp_idx[1]],
                                    (const float*)d_in[tp_idx[2]]);
    }
    // 3: pair table, level 3
    {
        dim3 grid((257 + 127) / 128, 1026, 3);          // (3, 1026, 3)
        pairv_kernel<<<grid, 128>>>((const float*)d_in[tp_idx[3]]);
    }

    // 4: encB first (level-3 table is L2-warm from the build)
    {
        long long threads = 6LL * N;
        encB_kernel<<<(int)((threads + 255) / 256), 256>>>(x, (float*)d_out, N);
    }
    // 5: encA (levels 0-2; tables only 16.6MB)
    {
        long long threads = 18LL * N;
        encA_kernel<<<(int)((threads + 255) / 256), 256>>>(x, (float*)d_out, N);
    }
}

// round 17
// speedup vs baseline: 1.4997x; 1.4997x over previous
#include <cuda_runtime.h>
#include <cuda_fp16.h>
#include <math.h>

// Levels: RES = {128, 256, 512, 1024}, C=4 channels, 3 planes per level.
//
// Plane storage: fp16 "quad table" per (level, plane), lc-prefolded, zero-
// bordered:  Quad[y][s] (32B, 32B-aligned) = 2x2 corner texels
//   { t(y-1,s-1), t(y-1,s), t(y,s-1), t(y,s) }, each texel 4ch fp16 = 8B.
// One bilinear sample at (ix,iy) reads Quad[iy+1][ix+1] = 2 LDG.128 in the
// SAME 32B sector. enc uses 8 threads/point (pair-lane row split, R13-best).
// Output stores use __stwt (write-through, no L2 allocation) so the 201MB
// write stream does not evict the L2-resident table.
#define NLEV 4

// quads per level: 3*(R+1)^2 -> 49923,198147,789507,3151875 ; total 4189452 (~134MB)
__device__ __align__(32) uint4 g_quads[8378904];   // 2 uint4 per quad
__device__ __align__(16) float g_linec[48];        // [l][p][c]

__constant__ int   c_res[NLEV]  = {128, 256, 512, 1024};
__constant__ int   c_qlvl[NLEV] = {0, 49923, 248070, 1037577};

// per-sample (s = l*3+p) prefolded params: qbase = qlvl[l] + p*(R+1)^2
__constant__ int c_sbase[12] = {
    0,       16641,   33282,
    49923,   115972,  182021,
    248070,  511239,  774408,
    1037577, 2088202, 3138827};
__constant__ int   c_srp[12] = {129,129,129, 257,257,257, 513,513,513, 1025,1025,1025};
__constant__ float c_shR[12] = {64.f,64.f,64.f, 128.f,128.f,128.f,
                                256.f,256.f,256.f, 512.f,512.f,512.f};
__constant__ int c_spn[12] = {0,1,2, 0,1,2, 0,1,2, 0,1,2};

// bit-reinterpret helpers (no-op in SASS)
__device__ __forceinline__ unsigned int h2_as_u32(__half2 h) {
    return *reinterpret_cast<unsigned int*>(&h);
}
__device__ __forceinline__ __half2 u32_as_h2(unsigned int u) {
    return *reinterpret_cast<__half2*>(&u);
}

// ---------------------------------------------------------------------------
// Line constants: triline grid_sample degenerates to
//   linec[l,p,c] = 0.5*(tl[p,c,R/2-1,0] + tl[p,c,R/2,0])
// ---------------------------------------------------------------------------
__global__ void linec_kernel(const float* __restrict__ t0, const float* __restrict__ t1,
                             const float* __restrict__ t2, const float* __restrict__ t3) {
    int i = threadIdx.x;
    if (i >= 48) return;
    int l  = i / 12;
    int pc = i % 12;            // p*4 + c
    const float* t = (l == 0) ? t0 : (l == 1) ? t1 : (l == 2) ? t2 : t3;
    int r = c_res[l];
    g_linec[i] = 0.5f * (t[pc * r + r / 2 - 1] + t[pc * r + r / 2]);
}

// ---------------------------------------------------------------------------
// Vectorized quad builder: each thread builds 4 consecutive quads (s0..s0+3).
// grid: (ceil((R/4+1)/128), R+1, 3*levels_in_launch) ; lvl = lvl0 + z/3, p = z%3
// ---------------------------------------------------------------------------
__global__ __launch_bounds__(128)
void quadv_kernel(const float* __restrict__ inA, const float* __restrict__ inB,
                  const float* __restrict__ inC, int lvl0) {
    int zi  = blockIdx.z;
    int li  = zi / 3;
    int lvl = lvl0 + li;
    int p   = zi % 3;
    int R   = c_res[lvl];
    int y   = blockIdx.y;
    if (y > R) return;
    int s0 = (blockIdx.x * blockDim.x + threadIdx.x) * 4;
    if (s0 > R) return;
    const float* in = (li == 0) ? inA : (li == 1) ? inB : inC;

    int rr = R * R;
    const float* bp = in + (size_t)(p * 4) * rr;
    const float* lc = g_linec + lvl * 12 + p * 4;

    int ylo = y - 1, yhi = y;
    bool ylov  = (ylo >= 0);
    bool yhiv  = (yhi < R);
    bool fullv = (s0 + 4 <= R);
    bool m1v   = (s0 >= 1);

    float wlo[4][5], whi[4][5];
#pragma unroll
    for (int c = 0; c < 4; c++) {
        float l_ = lc[c];
        const float* rl = bp + (size_t)c * rr + (size_t)ylo * R;
        const float* rh = bp + (size_t)c * rr + (size_t)yhi * R;
        float  m1l = (ylov && m1v) ? __ldg(rl + s0 - 1) : 0.f;
        float  m1h = (yhiv && m1v) ? __ldg(rh + s0 - 1) : 0.f;
        float4 vl = make_float4(0.f, 0.f, 0.f, 0.f);
        float4 vh = make_float4(0.f, 0.f, 0.f, 0.f);
        if (ylov && fullv) vl = __ldg(reinterpret_cast<const float4*>(rl + s0));
        if (yhiv && fullv) vh = __ldg(reinterpret_cast<const float4*>(rh + s0));
        wlo[c][0] = m1l * l_; wlo[c][1] = vl.x * l_; wlo[c][2] = vl.y * l_;
        wlo[c][3] = vl.z * l_; wlo[c][4] = vl.w * l_;
        whi[c][0] = m1h * l_; whi[c][1] = vh.x * l_; whi[c][2] = vh.y * l_;
        whi[c][3] = vh.z * l_; whi[c][4] = vh.w * l_;
    }

    int rp = R + 1;
    int qbase = c_qlvl[lvl] + p * rp * rp + y * rp + s0;
#pragma unroll
    for (int j = 0; j < 4; j++) {
        if (s0 + j > R) break;
        uint4 t0, t1;
        t0.x = h2_as_u32(__halves2half2(__float2half_rn(wlo[0][j]),     __float2half_rn(wlo[1][j])));
        t0.y = h2_as_u32(__halves2half2(__float2half_rn(wlo[2][j]),     __float2half_rn(wlo[3][j])));
        t0.z = h2_as_u32(__halves2half2(__float2half_rn(wlo[0][j + 1]), __float2half_rn(wlo[1][j + 1])));
        t0.w = h2_as_u32(__halves2half2(__float2half_rn(wlo[2][j + 1]), __float2half_rn(wlo[3][j + 1])));
        t1.x = h2_as_u32(__halves2half2(__float2half_rn(whi[0][j]),     __float2half_rn(whi[1][j])));
        t1.y = h2_as_u32(__halves2half2(__float2half_rn(whi[2][j]),     __float2half_rn(whi[3][j])));
        t1.z = h2_as_u32(__halves2half2(__float2half_rn(whi[0][j + 1]), __float2half_rn(whi[1][j + 1])));
        t1.w = h2_as_u32(__halves2half2(__float2half_rn(whi[2][j + 1]), __float2half_rn(whi[3][j + 1])));
        g_quads[2 * (qbase + j)]     = t0;
        g_quads[2 * (qbase + j) + 1] = t1;
    }
}

// ---------------------------------------------------------------------------
// Main kernel: 8 threads per point. Pair (2j, 2j+1) handles sample s = j+4r
// per round r=0..2; even lane loads quad row y0, odd lane row y1. Rows are
// exchanged via shfl_xor(1); even lane finalizes channels 0-1, odd lane
// channels 2-3 (8B write-through store each; sector-aligned per warp).
// ---------------------------------------------------------------------------
__global__ __launch_bounds__(256)
void enc_kernel(const float* __restrict__ x, float* __restrict__ out, int N) {
    int tid   = blockIdx.x * blockDim.x + threadIdx.x;
    int point = tid >> 3;
    bool live = (point < N);
    if (point >= N) point = N - 1;     // clamp: keep all lanes active for shfl
    int t   = tid & 7;
    int j   = t >> 1;                  // pair id 0..3
    int row = t & 1;                   // 0 = row y0, 1 = row y1

    const float* xp = x + 3 * (size_t)point;
    float px = fmaf(2.f, __ldg(xp + 0), -1.f);
    float py = fmaf(2.f, __ldg(xp + 1), -1.f);
    float pz = fmaf(2.f, __ldg(xp + 2), -1.f);

    float2* o2 = reinterpret_cast<float2*>(out + (size_t)point * 48);

#pragma unroll
    for (int r = 0; r < 3; r++) {
        int s = j + 4 * r;             // sample id 0..11

        int   base = c_sbase[s];
        int   rp   = c_srp[s];
        float hR   = c_shR[s];
        int   p    = c_spn[s];

        // plane p: (u=width, v=height) per projections (xz), (yx), (zy)
        float u  = (p == 0) ? px : (p == 1) ? py : pz;
        float v  = (p == 0) ? pz : (p == 1) ? px : py;
        float wl = fmaf(-0.5f, fabsf(u), 1.f);

        float fx = fmaf(u, hR, hR - 0.5f);
        float fy = fmaf(v, hR, hR - 0.5f);
        float fx0 = floorf(fx), fy0 = floorf(fy);
        float wx = fx - fx0,   wy = fy - fy0;
        int ix = (int)fx0, iy = (int)fy0;

        int qidx = base + (iy + 1) * rp + (ix + 1);
        uint4 tq = __ldg(&g_quads[2 * qidx + row]);   // my row: (x0 c01,c23),(x1 c01,c23)

        __half2 wx2 = __float2half2_rn(wx);
        __half2 a01 = u32_as_h2(tq.x), a23 = u32_as_h2(tq.y);   // x0
        __half2 b01 = u32_as_h2(tq.z), b23 = u32_as_h2(tq.w);   // x1

        // x-lerp my row
        __half2 r01 = __hfma2(__hsub2(b01, a01), wx2, a01);
        __half2 r23 = __hfma2(__hsub2(b23, a23), wx2, a23);

        // exchange with partner row
        unsigned o01 = __shfl_xor_sync(0xffffffffu, h2_as_u32(r01), 1);
        unsigned o23 = __shfl_xor_sync(0xffffffffu, h2_as_u32(r23), 1);

        // even lane (row 0): channels 0-1 ; odd lane (row 1): channels 2-3
        __half2 lo = (row == 0) ? r01 : u32_as_h2(o23);
        __half2 hi = (row == 0) ? u32_as_h2(o01) : r23;

        __half2 wy2 = __float2half2_rn(wy);
        __half2 vv2 = __hfma2(__hsub2(hi, lo), wy2, lo);
        float2 f = __half22float2(vv2);

        float2 res;
        res.x = f.x * wl;
        res.y = f.y * wl;
        if (live) __stwt(&o2[s * 2 + row], res);   // write-through: no L2 allocation
    }
}

// ---------------------------------------------------------------------------
// Launch: identify inputs by size (robust to metadata ordering)
// ---------------------------------------------------------------------------
extern "C" void kernel_launch(void* const* d_in, const int* in_sizes, int n_in,
                              void* d_out, int out_size) {
    // triplane_l : 12*R*R = 196608, 786432, 3145728, 12582912
    // triline_l  : 12*R   = 1536, 3072, 6144, 12288
    // x          : 3*N    = 3145728 (ambiguous with triplane_2)
    int tp_idx[NLEV] = {-1, -1, -1, -1};
    int tl_idx[NLEV] = {-1, -1, -1, -1};
    int amb[2]; int n_amb = 0;
    int x_idx = -1;

    for (int i = 0; i < n_in; i++) {
        int s = in_sizes[i];
        if      (s == 196608)   tp_idx[0] = i;
        else if (s == 786432)   tp_idx[1] = i;
        else if (s == 12582912) tp_idx[3] = i;
        else if (s == 1536)     tl_idx[0] = i;
        else if (s == 3072)     tl_idx[1] = i;
        else if (s == 6144)     tl_idx[2] = i;
        else if (s == 12288)    tl_idx[3] = i;
        else if (s == 3145728)  { if (n_amb < 2) amb[n_amb++] = i; }
        else if (x_idx < 0)     x_idx = i;
    }
    if (n_amb == 1) {
        tp_idx[2] = amb[0];
    } else if (n_amb == 2) {
        // triplane_0..3 occupy contiguous ascending indices in either ordering
        int a = amb[0], b = amb[1];
        if (a > tp_idx[1] && a < tp_idx[3]) { tp_idx[2] = a; x_idx = b; }
        else                                { tp_idx[2] = b; x_idx = a; }
    }
    if (x_idx < 0) x_idx = 0;

    const float* x = (const float*)d_in[x_idx];
    int N = in_sizes[x_idx] / 3;

    // Launch 1: line constants (folded into quad tables)
    linec_kernel<<<1, 64>>>((const float*)d_in[tl_idx[0]], (const float*)d_in[tl_idx[1]],
                            (const float*)d_in[tl_idx[2]], (const float*)d_in[tl_idx[3]]);

    // Launch 2: quad tables, levels 0-2 fused
    {
        dim3 grid((512 / 4 + 1 + 127) / 128, 513, 9);   // (2, 513, 9)
        quadv_kernel<<<grid, 128>>>((const float*)d_in[tp_idx[0]],
                                    (const float*)d_in[tp_idx[1]],
                                    (const float*)d_in[tp_idx[2]], 0);
    }
    // Launch 3: quad table, level 3 (R=1024)
    {
        dim3 grid((1024 / 4 + 1 + 127) / 128, 1025, 3); // (3, 1025, 3)
        const float* t3 = (const float*)d_in[tp_idx[3]];
        quadv_kernel<<<grid, 128>>>(t3, t3, t3, 3);
    }

    // Launch 4: main pass (8 threads per point)
    long long threads = 8LL * N;
    enc_kernel<<<(int)((threads + 255) / 256), 256>>>(x, (float*)d_out, N);
}